// round 6
// baseline (speedup 1.0000x reference)
#include <cuda_runtime.h>
#include <cuda_bf16.h>

#define NN 50000
#define EE 1600000
#define ET (EE + NN)   // edges + self loops
#define IN_CH 128
#define H1C1 32        // 4 heads * 8
#define OUT_CH 64

// ---------------- scratch (device globals; no allocation allowed) ----------------
__device__ int2  g_edge[ET];             // (src, dst) int32, self-loops appended
__device__ float g_h1[NN * H1C1];        // x @ W1            [N,4,8]
__device__ float g_asrc1[NN * 4];
__device__ float g_adst1[NN * 4];
__device__ float g_s1[NN * 4];           // softmax denominators (layer 1)
__device__ float g_agg1[NN * H1C1];      // unnormalized layer-1 aggregation
__device__ float g_h2[NN * OUT_CH];      // relu(norm(agg1)+b1) @ W2
__device__ float g_asrc2[NN];
__device__ float g_adst2[NN];
__device__ float g_s2[NN];               // softmax denominators (layer 2)

// ---------------- edge list conversion: int32 [2,E] -> int2, + self loops ----------
// NOTE: reference uses jnp.int64 but default JAX demotes to int32 -> const int*.
__global__ void prep_edges(const int* __restrict__ ei) {
    int e = blockIdx.x * blockDim.x + threadIdx.x;
    if (e >= ET) return;
    int2 p;
    if (e < EE) { p.x = ei[e]; p.y = ei[EE + e]; }
    else        { p.x = p.y = e - EE; }
    g_edge[e] = p;
}

// ---------------- layer 1 GEMM: h1 = x @ W1  (128 -> 32) ----------------
__global__ void gemm1_kernel(const float* __restrict__ x, const float* __restrict__ W1) {
    __shared__ float Ws[IN_CH * H1C1];   // 16 KB
    __shared__ float xs[8][IN_CH];
    int tid = threadIdx.x;
    for (int i = tid; i < IN_CH * H1C1; i += 256) Ws[i] = W1[i];
    int ty = tid >> 5, lane = tid & 31;
    int row = blockIdx.x * 8 + ty;
    if (row < NN) {
        #pragma unroll
        for (int k = lane; k < IN_CH; k += 32) xs[ty][k] = x[row * IN_CH + k];
    }
    __syncthreads();
    if (row < NN) {
        float acc = 0.f;
        #pragma unroll
        for (int k = 0; k < IN_CH; k++) acc += xs[ty][k] * Ws[k * H1C1 + lane];
        g_h1[row * H1C1 + lane] = acc;
    }
}

// ---------------- layer 1 attention coefficients + zero accumulators -------------
__global__ void att1_kernel(const float* __restrict__ att_src1, const float* __restrict__ att_dst1) {
    int i = blockIdx.x * blockDim.x + threadIdx.x;   // i = n*4 + h
    if (i >= NN * 4) return;
    int h = i & 3;
    const float* hp = g_h1 + (i >> 2) * H1C1 + h * 8;
    float s = 0.f, d = 0.f;
    #pragma unroll
    for (int c = 0; c < 8; c++) {
        float v = hp[c];
        s += v * att_src1[h * 8 + c];
        d += v * att_dst1[h * 8 + c];
    }
    g_asrc1[i] = s;
    g_adst1[i] = d;
    g_s1[i] = 0.f;
    #pragma unroll
    for (int c = 0; c < 8; c++) g_agg1[(i >> 2) * H1C1 + h * 8 + c] = 0.f;
}

// ---------------- layer 1 fused edge pass (warp per edge) ----------------
// Accumulates unnormalized weighted messages + denominators in ONE pass.
__global__ void edge1_fused() {
    int e = (blockIdx.x * blockDim.x + threadIdx.x) >> 5;
    int lane = threadIdx.x & 31;
    if (e >= ET) return;
    int2 p = g_edge[e];
    int src = p.x, dst = p.y;
    int h = lane >> 3;                          // head for this lane's channel
    float l = __ldg(&g_asrc1[src * 4 + h]) + __ldg(&g_adst1[dst * 4 + h]);
    l = l > 0.f ? l : 0.2f * l;                 // leaky relu
    float w = __expf(l);                        // logits bounded; max-shift omitted
    if ((lane & 7) == 0) atomicAdd(&g_s1[dst * 4 + h], w);
    atomicAdd(&g_agg1[dst * H1C1 + lane], __ldg(&g_h1[src * H1C1 + lane]) * w);
}

// ---------------- layer 2 GEMM: h2 = relu(agg1/s1 + b1) @ W2  (32 -> 64) --------
__global__ void gemm2_kernel(const float* __restrict__ W2, const float* __restrict__ b1) {
    __shared__ float Ws[H1C1 * OUT_CH];  // 8 KB
    __shared__ float xs[4][H1C1];
    int tid = threadIdx.x;
    for (int i = tid; i < H1C1 * OUT_CH; i += 256) Ws[i] = W2[i];
    int ty = tid >> 6, col = tid & 63;
    int row = blockIdx.x * 4 + ty;
    if (row < NN && col < H1C1) {
        float v = g_agg1[row * H1C1 + col] / (g_s1[row * 4 + (col >> 3)] + 1e-16f) + b1[col];
        xs[ty][col] = fmaxf(v, 0.f);
    }
    __syncthreads();
    if (row < NN) {
        float acc = 0.f;
        #pragma unroll
        for (int k = 0; k < H1C1; k++) acc += xs[ty][k] * Ws[k * OUT_CH + col];
        g_h2[row * OUT_CH + col] = acc;
    }
}

// ---------------- layer 2 attention coefficients (warp per node) ----------------
__global__ void att2_kernel(const float* __restrict__ att_src2, const float* __restrict__ att_dst2) {
    int warp = (blockIdx.x * blockDim.x + threadIdx.x) >> 5;
    int lane = threadIdx.x & 31;
    if (warp >= NN) return;
    float s = 0.f, d = 0.f;
    #pragma unroll
    for (int c = lane; c < OUT_CH; c += 32) {
        float v = g_h2[warp * OUT_CH + c];
        s += v * att_src2[c];
        d += v * att_dst2[c];
    }
    #pragma unroll
    for (int o = 16; o; o >>= 1) {
        s += __shfl_down_sync(0xFFFFFFFFu, s, o);
        d += __shfl_down_sync(0xFFFFFFFFu, d, o);
    }
    if (lane == 0) { g_asrc2[warp] = s; g_adst2[warp] = d; g_s2[warp] = 0.f; }
}

// ---------------- zero output accumulator ----------------
__global__ void init2_kernel(float* __restrict__ out) {
    int i = blockIdx.x * blockDim.x + threadIdx.x;
    if (i < NN * OUT_CH) out[i] = 0.f;
}

// ---------------- layer 2 fused edge pass (warp per edge) ----------------
__global__ void edge2_fused(float* __restrict__ out) {
    int e = (blockIdx.x * blockDim.x + threadIdx.x) >> 5;
    int lane = threadIdx.x & 31;
    if (e >= ET) return;
    int2 p = g_edge[e];
    int src = p.x, dst = p.y;
    float l = __ldg(&g_asrc2[src]) + __ldg(&g_adst2[dst]);
    l = l > 0.f ? l : 0.2f * l;
    float w = __expf(l);
    if (lane == 0) atomicAdd(&g_s2[dst], w);
    atomicAdd(&out[dst * OUT_CH + lane],      __ldg(&g_h2[src * OUT_CH + lane])      * w);
    atomicAdd(&out[dst * OUT_CH + lane + 32], __ldg(&g_h2[src * OUT_CH + lane + 32]) * w);
}

// ---------------- finalize: normalize + bias ----------------
__global__ void finalize2(float* __restrict__ out, const float* __restrict__ b2) {
    int i = blockIdx.x * blockDim.x + threadIdx.x;
    if (i >= NN * OUT_CH) return;
    out[i] = out[i] / (g_s2[i >> 6] + 1e-16f) + b2[i & 63];
}

extern "C" void kernel_launch(void* const* d_in, const int* in_sizes, int n_in,
                              void* d_out, int out_size) {
    const float* x        = (const float*)d_in[0];
    const int*   ei       = (const int*)d_in[1];      // int32 (JAX x64 disabled)
    const float* W1       = (const float*)d_in[2];
    const float* att_src1 = (const float*)d_in[3];
    const float* att_dst1 = (const float*)d_in[4];
    const float* b1       = (const float*)d_in[5];
    const float* W2       = (const float*)d_in[6];
    const float* att_src2 = (const float*)d_in[7];
    const float* att_dst2 = (const float*)d_in[8];
    const float* b2       = (const float*)d_in[9];
    float* out = (float*)d_out;

    prep_edges<<<(ET + 255) / 256, 256>>>(ei);

    // ---- layer 1 ----
    gemm1_kernel<<<(NN + 7) / 8, 256>>>(x, W1);
    att1_kernel<<<(NN * 4 + 255) / 256, 256>>>(att_src1, att_dst1);
    edge1_fused<<<(ET * 32 + 255) / 256, 256>>>();

    // ---- layer 2 ----
    gemm2_kernel<<<(NN + 3) / 4, 256>>>(W2, b1);
    att2_kernel<<<(NN * 32 + 255) / 256, 256>>>(att_src2, att_dst2);
    init2_kernel<<<(NN * OUT_CH + 255) / 256, 256>>>(out);
    edge2_fused<<<(ET * 32 + 255) / 256, 256>>>(out);
    finalize2<<<(NN * OUT_CH + 255) / 256, 256>>>(out, b2);
}

// round 7
// speedup vs baseline: 1.4090x; 1.4090x over previous
#include <cuda_runtime.h>
#include <cuda_bf16.h>

#define NN 50000
#define EE 1600000
#define ET (EE + NN)   // edges + self loops
#define IN_CH 128
#define H1C1 32        // 4 heads * 8
#define OUT_CH 64

// ---------------- scratch (device globals; no allocation allowed) ----------------
__device__ int2  g_edge[ET];             // (src, dst) int32, self-loops appended
__device__ float g_h1[NN * H1C1];        // x @ W1            [N,4,8]
__device__ float g_asrc1[NN * 4];
__device__ float g_adst1[NN * 4];
__device__ float g_s1[NN * 4];           // softmax denominators (layer 1)
__device__ float g_agg1[NN * H1C1];      // unnormalized layer-1 aggregation
__device__ float g_h2[NN * OUT_CH];      // relu(norm(agg1)+b1) @ W2
__device__ float g_asrc2[NN];
__device__ float g_adst2[NN];
__device__ float g_s2[NN];               // softmax denominators (layer 2)

// vectorized fp32 reduction (sm_90+): 1 instruction, 16 bytes
__device__ __forceinline__ void red_add_v4(float* p, float4 v) {
    asm volatile("red.global.add.v4.f32 [%0], {%1, %2, %3, %4};"
                 :: "l"(p), "f"(v.x), "f"(v.y), "f"(v.z), "f"(v.w) : "memory");
}

// ---------------- edge list conversion: int32 [2,E] -> int2, + self loops ----------
__global__ void prep_edges(const int* __restrict__ ei) {
    int e = blockIdx.x * blockDim.x + threadIdx.x;
    if (e >= ET) return;
    int2 p;
    if (e < EE) { p.x = ei[e]; p.y = ei[EE + e]; }
    else        { p.x = p.y = e - EE; }
    g_edge[e] = p;
}

// ---------------- layer 1 GEMM: h1 = x @ W1  (128 -> 32) ----------------
__global__ void gemm1_kernel(const float* __restrict__ x, const float* __restrict__ W1) {
    __shared__ float Ws[IN_CH * H1C1];   // 16 KB
    __shared__ float xs[8][IN_CH];
    int tid = threadIdx.x;
    for (int i = tid; i < IN_CH * H1C1; i += 256) Ws[i] = W1[i];
    int ty = tid >> 5, lane = tid & 31;
    int row = blockIdx.x * 8 + ty;
    if (row < NN) {
        #pragma unroll
        for (int k = lane; k < IN_CH; k += 32) xs[ty][k] = x[row * IN_CH + k];
    }
    __syncthreads();
    if (row < NN) {
        float acc = 0.f;
        #pragma unroll
        for (int k = 0; k < IN_CH; k++) acc += xs[ty][k] * Ws[k * H1C1 + lane];
        g_h1[row * H1C1 + lane] = acc;
    }
}

// ---------------- layer 1 attention coefficients + zero accumulators -------------
__global__ void att1_kernel(const float* __restrict__ att_src1, const float* __restrict__ att_dst1) {
    int i = blockIdx.x * blockDim.x + threadIdx.x;   // i = n*4 + h
    if (i >= NN * 4) return;
    int h = i & 3;
    const float* hp = g_h1 + (i >> 2) * H1C1 + h * 8;
    float s = 0.f, d = 0.f;
    #pragma unroll
    for (int c = 0; c < 8; c++) {
        float v = hp[c];
        s += v * att_src1[h * 8 + c];
        d += v * att_dst1[h * 8 + c];
    }
    g_asrc1[i] = s;
    g_adst1[i] = d;
    g_s1[i] = 0.f;
    #pragma unroll
    for (int c = 0; c < 8; c++) g_agg1[(i >> 2) * H1C1 + h * 8 + c] = 0.f;
}

// ---------------- layer 1 fused edge pass: 8 threads / edge, float4 payload ------
__global__ void edge1_fused() {
    int t = blockIdx.x * blockDim.x + threadIdx.x;
    int e = t >> 3;
    if (e >= ET) return;
    int sub = t & 7;                            // float4 chunk: channels sub*4..sub*4+3
    int2 p = g_edge[e];
    int h = sub >> 1;                           // head = (sub*4)/8
    float l = __ldg(&g_asrc1[p.x * 4 + h]) + __ldg(&g_adst1[p.y * 4 + h]);
    l = l > 0.f ? l : 0.2f * l;                 // leaky relu
    float w = __expf(l);                        // logits bounded; max-shift omitted
    if ((sub & 1) == 0) atomicAdd(&g_s1[p.y * 4 + h], w);
    float4 v = *reinterpret_cast<const float4*>(&g_h1[p.x * H1C1 + sub * 4]);
    red_add_v4(&g_agg1[p.y * H1C1 + sub * 4],
               make_float4(v.x * w, v.y * w, v.z * w, v.w * w));
}

// ---------------- layer 2 GEMM: h2 = relu(agg1/s1 + b1) @ W2  (32 -> 64) --------
__global__ void gemm2_kernel(const float* __restrict__ W2, const float* __restrict__ b1) {
    __shared__ float Ws[H1C1 * OUT_CH];  // 8 KB
    __shared__ float xs[4][H1C1];
    int tid = threadIdx.x;
    for (int i = tid; i < H1C1 * OUT_CH; i += 256) Ws[i] = W2[i];
    int ty = tid >> 6, col = tid & 63;
    int row = blockIdx.x * 4 + ty;
    if (row < NN && col < H1C1) {
        float v = g_agg1[row * H1C1 + col] / (g_s1[row * 4 + (col >> 3)] + 1e-16f) + b1[col];
        xs[ty][col] = fmaxf(v, 0.f);
    }
    __syncthreads();
    if (row < NN) {
        float acc = 0.f;
        #pragma unroll
        for (int k = 0; k < H1C1; k++) acc += xs[ty][k] * Ws[k * OUT_CH + col];
        g_h2[row * OUT_CH + col] = acc;
    }
}

// ---------------- layer 2 attention coefficients (warp per node) ----------------
__global__ void att2_kernel(const float* __restrict__ att_src2, const float* __restrict__ att_dst2) {
    int warp = (blockIdx.x * blockDim.x + threadIdx.x) >> 5;
    int lane = threadIdx.x & 31;
    if (warp >= NN) return;
    float s = 0.f, d = 0.f;
    #pragma unroll
    for (int c = lane; c < OUT_CH; c += 32) {
        float v = g_h2[warp * OUT_CH + c];
        s += v * att_src2[c];
        d += v * att_dst2[c];
    }
    #pragma unroll
    for (int o = 16; o; o >>= 1) {
        s += __shfl_down_sync(0xFFFFFFFFu, s, o);
        d += __shfl_down_sync(0xFFFFFFFFu, d, o);
    }
    if (lane == 0) { g_asrc2[warp] = s; g_adst2[warp] = d; g_s2[warp] = 0.f; }
}

// ---------------- zero output accumulator ----------------
__global__ void init2_kernel(float* __restrict__ out) {
    int i = blockIdx.x * blockDim.x + threadIdx.x;
    if (i < NN * OUT_CH) out[i] = 0.f;
}

// ---------------- layer 2 fused edge pass: 16 threads / edge, float4 payload -----
__global__ void edge2_fused(float* __restrict__ out) {
    int t = blockIdx.x * blockDim.x + threadIdx.x;
    int e = t >> 4;
    if (e >= ET) return;
    int sub = t & 15;                           // channels sub*4..sub*4+3
    int2 p = g_edge[e];
    float l = __ldg(&g_asrc2[p.x]) + __ldg(&g_adst2[p.y]);
    l = l > 0.f ? l : 0.2f * l;
    float w = __expf(l);
    if (sub == 0) atomicAdd(&g_s2[p.y], w);
    float4 v = *reinterpret_cast<const float4*>(&g_h2[p.x * OUT_CH + sub * 4]);
    red_add_v4(&out[p.y * OUT_CH + sub * 4],
               make_float4(v.x * w, v.y * w, v.z * w, v.w * w));
}

// ---------------- finalize: normalize + bias ----------------
__global__ void finalize2(float* __restrict__ out, const float* __restrict__ b2) {
    int i = blockIdx.x * blockDim.x + threadIdx.x;
    if (i >= NN * OUT_CH) return;
    out[i] = out[i] / (g_s2[i >> 6] + 1e-16f) + b2[i & 63];
}

extern "C" void kernel_launch(void* const* d_in, const int* in_sizes, int n_in,
                              void* d_out, int out_size) {
    const float* x        = (const float*)d_in[0];
    const int*   ei       = (const int*)d_in[1];      // int32 (JAX x64 disabled)
    const float* W1       = (const float*)d_in[2];
    const float* att_src1 = (const float*)d_in[3];
    const float* att_dst1 = (const float*)d_in[4];
    const float* b1       = (const float*)d_in[5];
    const float* W2       = (const float*)d_in[6];
    const float* att_src2 = (const float*)d_in[7];
    const float* att_dst2 = (const float*)d_in[8];
    const float* b2       = (const float*)d_in[9];
    float* out = (float*)d_out;

    prep_edges<<<(ET + 255) / 256, 256>>>(ei);

    // ---- layer 1 ----
    gemm1_kernel<<<(NN + 7) / 8, 256>>>(x, W1);
    att1_kernel<<<(NN * 4 + 255) / 256, 256>>>(att_src1, att_dst1);
    edge1_fused<<<((long long)ET * 8 + 255) / 256, 256>>>();

    // ---- layer 2 ----
    gemm2_kernel<<<(NN + 3) / 4, 256>>>(W2, b1);
    att2_kernel<<<(NN * 32 + 255) / 256, 256>>>(att_src2, att_dst2);
    init2_kernel<<<(NN * OUT_CH + 255) / 256, 256>>>(out);
    edge2_fused<<<((long long)ET * 16 + 255) / 256, 256>>>(out);
    finalize2<<<(NN * OUT_CH + 255) / 256, 256>>>(out, b2);
}